// round 17
// baseline (speedup 1.0000x reference)
#include <cuda_runtime.h>
#include <cuda_fp16.h>
#include <math.h>
#include <stdint.h>

#define CIN   64
#define COUT  128
#define HH    128
#define WW    128
#define NB    32

// ---------------- persistent scratch (__device__ globals) -------------------
__device__ uint4 g_x1[(size_t)NB * HH * 1024];   // [n][h][pix(128)][ic(64)] fp16
// U in mma-fragment-linear order: [pos(16)][warp(8)][kc(4)][lane(32)] x uint4
// (corner pos 3,12 sign-folded at prep time)
__device__ uint4 g_uf[16 * 8 * 4 * 32];

// ---------------- fused pre-pass: blocks 0..31 = U, 32..4127 = x ------------
__global__ void prep_all(const float* __restrict__ w,
                         const float* __restrict__ x) {
    __shared__ __half sh[128 * 72];
    const int bid = blockIdx.x;

    if (bid < 32) {
        // ---- Winograd U (fp32-exact -> fp16), scattered to fragment layout --
        int idx = bid * 256 + threadIdx.x;          // 0..8191 = oc*64+ic
        if (idx >= COUT * CIN) return;
        int oc = idx >> 6, ic = idx & 63;
        float g[3][3];
#pragma unroll
        for (int r = 0; r < 3; r++)
#pragma unroll
            for (int c = 0; c < 3; c++)
                g[r][c] = w[((size_t)(ic * COUT + oc) * 3 + (2 - r)) * 3 + (2 - c)];
        float t[4][3];
#pragma unroll
        for (int c = 0; c < 3; c++) {
            t[0][c] = g[0][c];
            t[1][c] = 0.5f * (g[0][c] + g[1][c] + g[2][c]);
            t[2][c] = 0.5f * (g[0][c] - g[1][c] + g[2][c]);
            t[3][c] = g[2][c];
        }
        // fragment scatter coordinates for this (oc, ic)
        const int ws = oc >> 4;
        const int l  = ((oc & 7) << 2) | ((ic & 7) >> 1);
        const int reg = ((oc >> 3) & 1) | (((ic >> 3) & 1) << 1);
        const int kc = ic >> 4;
        const int h  = ic & 1;
        __half* dst = (__half*)g_uf;
#pragma unroll
        for (int r = 0; r < 4; r++) {
            float u[4];
            u[0] = t[r][0];
            u[1] = 0.5f * (t[r][0] + t[r][1] + t[r][2]);
            u[2] = 0.5f * (t[r][0] - t[r][1] + t[r][2]);
            u[3] = t[r][2];
            if (r == 3) u[0] = -u[0];       // pos 12 = (3,0): a-coef -1
            if (r == 0) u[3] = -u[3];       // pos 3  = (0,3): b-coef -1
#pragma unroll
            for (int cc = 0; cc < 4; cc++) {
                int pos = r * 4 + cc;
                size_t hidx = ((((size_t)(pos * 8 + ws) * 4 + kc) * 32 + l) * 4
                               + reg) * 2 + h;
                dst[hidx] = __float2half_rn(u[cc]);
            }
        }
        return;
    }

    // ---- x -> fp16 transposed tiles ----
    const int r2 = bid - 32;
    const int h = r2 & 127, n = r2 >> 7;
    const float* xb = x + (size_t)n * CIN * HH * WW;
#pragma unroll
    for (int i = 0; i < 8; i++) {
        int f = threadIdx.x + i * 256;
        int ic = f >> 5, p4 = f & 31;
        float4 v = *(const float4*)(xb + ((size_t)ic * HH + h) * WW + p4 * 4);
        float vv[4] = {v.x, v.y, v.z, v.w};
#pragma unroll
        for (int j = 0; j < 4; j++)
            sh[(p4 * 4 + j) * 72 + ic] = __float2half_rn(vv[j]);
    }
    __syncthreads();
    uint4* dst = g_x1 + (size_t)(n * HH + h) * 1024;
    for (int q = threadIdx.x; q < 1024; q += 256) {
        int p = q >> 3, c = q & 7;
        dst[q] = *(const uint4*)((const char*)sh + p * 144 + c * 16);
    }
}

// ---------------- main kernel ----------------------------------------------
// CTA = output rows {2hb, 2hb+1} x 64 pixels (32 Winograd tiles).
// smem: V [16 pos][32 tiles][128B swz] = 65536 (nothing else).
#define VPOS_B 4096
#define SMEM_SZ 65536

static __device__ __forceinline__ unsigned smem_u32(const void* p) {
    unsigned r;
    asm("{ .reg .u64 t; cvta.to.shared.u64 t, %1; cvt.u32.u64 %0, t; }"
        : "=r"(r) : "l"(p));
    return r;
}
__device__ __forceinline__ void ldsm4(unsigned r[4], unsigned addr) {
    asm volatile("ldmatrix.sync.aligned.m8n8.x4.shared.b16 {%0,%1,%2,%3}, [%4];"
                 : "=r"(r[0]), "=r"(r[1]), "=r"(r[2]), "=r"(r[3]) : "r"(addr));
}
__device__ __forceinline__ void mma16816(float c[4], unsigned a0, unsigned a1,
                                         unsigned a2, unsigned a3,
                                         unsigned b0, unsigned b1) {
    asm volatile(
        "mma.sync.aligned.m16n8k16.row.col.f32.f16.f16.f32 "
        "{%0,%1,%2,%3}, {%4,%5,%6,%7}, {%8,%9}, {%0,%1,%2,%3};"
        : "+f"(c[0]), "+f"(c[1]), "+f"(c[2]), "+f"(c[3])
        : "r"(a0), "r"(a1), "r"(a2), "r"(a3), "r"(b0), "r"(b1));
}
__device__ __forceinline__ void mma16816_dc(float d[4], unsigned a0, unsigned a1,
                                            unsigned a2, unsigned a3,
                                            unsigned b0, unsigned b1,
                                            const float c[4]) {
    asm volatile(
        "mma.sync.aligned.m16n8k16.row.col.f32.f16.f16.f32 "
        "{%0,%1,%2,%3}, {%4,%5,%6,%7}, {%8,%9}, {%10,%11,%12,%13};"
        : "=f"(d[0]), "=f"(d[1]), "=f"(d[2]), "=f"(d[3])
        : "r"(a0), "r"(a1), "r"(a2), "r"(a3), "r"(b0), "r"(b1),
          "f"(c[0]), "f"(c[1]), "f"(c[2]), "f"(c[3]));
}
__device__ __forceinline__ float gelu_tanh(float y) {
    float u = 1.5957691216f * (y + 0.044715f * y * y * y);
    return __fdividef(y, 1.0f + __expf(-u));
}

extern __shared__ char dyn_smem[];

__global__ __launch_bounds__(256, 2)
void convt_wino_kernel(const float* __restrict__ bias,
                       const float* __restrict__ gnw,
                       const float* __restrict__ gnb,
                       float* __restrict__ out) {
    const int hb = blockIdx.x >> 1;     // output rows {2hb, 2hb+1}
    const int ps = blockIdx.x & 1;      // pixel slice: 64 px at ps*64
    const int n = blockIdx.y;
    const int tid = threadIdx.x;
    const int wid = tid >> 5;
    const int l = tid & 31;

    const unsigned sb = smem_u32(dyn_smem);

    // ---- V transform straight from gmem (coalesced __ldg), fp16 store ------
    // unit = (tile tl 0..31, ic-pair q 0..31); per warp: q = lane -> each
    // (i,jj) read is one contiguous 128B line.
#pragma unroll
    for (int jb = 0; jb < 4; jb++) {
        int idx = tid + jb * 256;       // 0..1023
        int tl = idx >> 5, q = idx & 31;
        const unsigned vxr = (unsigned)((tl & 7) << 4);
        float2 d[4][4];
#pragma unroll
        for (int i = 0; i < 4; i++) {
            int gh = 2 * hb - 2 + i;
            const char* rowb = (const char*)g_x1 +
                (size_t)(n * HH + (gh < 0 ? 0 : gh)) * 16384;
#pragma unroll
            for (int jj = 0; jj < 4; jj++) {
                int gp = ps * 64 + 2 * tl + jj - 2;
                bool ok = (gh >= 0) && (gp >= 0);
                __half2 hv = ok ? __ldg((const __half2*)
                                        (rowb + (size_t)gp * 128 + q * 4))
                                : __half2half2(__float2half(0.f));
                d[i][jj] = __half22float2(hv);
            }
        }
        float2 e[4][4];
#pragma unroll
        for (int jj = 0; jj < 4; jj++) {
            e[0][jj] = make_float2(d[0][jj].x - d[2][jj].x, d[0][jj].y - d[2][jj].y);
            e[1][jj] = make_float2(d[1][jj].x + d[2][jj].x, d[1][jj].y + d[2][jj].y);
            e[2][jj] = make_float2(d[2][jj].x - d[1][jj].x, d[2][jj].y - d[1][jj].y);
            e[3][jj] = make_float2(d[1][jj].x - d[3][jj].x, d[1][jj].y - d[3][jj].y);
        }
#pragma unroll
        for (int r = 0; r < 4; r++) {
            float2 v[4];
            v[0] = make_float2(e[r][0].x - e[r][2].x, e[r][0].y - e[r][2].y);
            v[1] = make_float2(e[r][1].x + e[r][2].x, e[r][1].y + e[r][2].y);
            v[2] = make_float2(e[r][2].x - e[r][1].x, e[r][2].y - e[r][1].y);
            v[3] = make_float2(e[r][1].x - e[r][3].x, e[r][1].y - e[r][3].y);
#pragma unroll
            for (int s = 0; s < 4; s++)
                *(__half2*)(dyn_smem + (r * 4 + s) * VPOS_B + tl * 128 +
                            (unsigned)((q * 4) ^ vxr)) =
                    __floats2half2_rn(v[s].x, v[s].y);
        }
    }
    __syncthreads();                    // the ONLY barrier in this kernel

    // ---- per-lane ldmatrix components (B from V smem) ----
    const int bRow = (l & 7) + ((l & 16) ? 8 : 0);
    const unsigned bXr = (unsigned)((bRow & 7) << 4);
    const unsigned bKoff = (l & 8) ? 16u : 0u;

    // A fragment gmem pointer for this (warp, lane)
    const uint4* Abase = g_uf + (size_t)wid * 4 * 32 + l;

    // ---- Y accumulators: [pi][tn][ab][c] ----
    float Y[2][2][4][4];
#pragma unroll
    for (int pi = 0; pi < 2; pi++)
#pragma unroll
        for (int tn = 0; tn < 2; tn++)
#pragma unroll
            for (int ab = 0; ab < 4; ab++)
#pragma unroll
                for (int c = 0; c < 4; c++) Y[pi][tn][ab][c] = 0.f;

    float zero4[4] = {0.f, 0.f, 0.f, 0.f};
    constexpr float AR[2][4] = {{1.f, 1.f, 1.f, 0.f}, {0.f, 1.f, -1.f, -1.f}};

    // ---- mainloop over 16 Winograd positions (A via LDG, no barriers) ------
#pragma unroll
    for (int p = 0; p < 16; p++) {
        const int pr = p >> 2, pc = p & 3;
        const bool corner = (pr == 0 || pr == 3) && (pc == 0 || pc == 3);
        const int cab = (pr ? 2 : 0) + (pc ? 1 : 0);
        const unsigned vb0 = sb + (unsigned)p * VPOS_B + (unsigned)bRow * 128;
        const unsigned vb1 = vb0 + 2048;

        // batched A-fragment loads for this pos (4 x LDG.128, MLP=4)
        uint4 av[4];
#pragma unroll
        for (int kc = 0; kc < 4; kc++)
            av[kc] = __ldg(Abase + (size_t)(p * 8) * 4 * 32 + kc * 32);

        if (corner) {
#pragma unroll
            for (int kc = 0; kc < 4; kc++) {
                unsigned b0[4], b1[4];
                const unsigned csw = ((unsigned)(kc * 32) + bKoff) ^ bXr;
                ldsm4(b0, vb0 + csw);
                ldsm4(b1, vb1 + csw);
                mma16816(Y[0][0][cab], av[kc].x, av[kc].y, av[kc].z, av[kc].w,
                         b0[0], b0[1]);
                mma16816(Y[0][1][cab], av[kc].x, av[kc].y, av[kc].z, av[kc].w,
                         b0[2], b0[3]);
                mma16816(Y[1][0][cab], av[kc].x, av[kc].y, av[kc].z, av[kc].w,
                         b1[0], b1[1]);
                mma16816(Y[1][1][cab], av[kc].x, av[kc].y, av[kc].z, av[kc].w,
                         b1[2], b1[3]);
            }
        } else {
            float tmp[2][2][4];
#pragma unroll
            for (int kc = 0; kc < 4; kc++) {
                unsigned b0[4], b1[4];
                const unsigned csw = ((unsigned)(kc * 32) + bKoff) ^ bXr;
                ldsm4(b0, vb0 + csw);
                ldsm4(b1, vb1 + csw);
                if (kc == 0) {
                    mma16816_dc(tmp[0][0], av[0].x, av[0].y, av[0].z, av[0].w,
                                b0[0], b0[1], zero4);
                    mma16816_dc(tmp[0][1], av[0].x, av[0].y, av[0].z, av[0].w,
                                b0[2], b0[3], zero4);
                    mma16816_dc(tmp[1][0], av[0].x, av[0].y, av[0].z, av[0].w,
                                b1[0], b1[1], zero4);
                    mma16816_dc(tmp[1][1], av[0].x, av[0].y, av[0].z, av[0].w,
                                b1[2], b1[3], zero4);
                } else {
                    mma16816(tmp[0][0], av[kc].x, av[kc].y, av[kc].z, av[kc].w,
                             b0[0], b0[1]);
                    mma16816(tmp[0][1], av[kc].x, av[kc].y, av[kc].z, av[kc].w,
                             b0[2], b0[3]);
                    mma16816(tmp[1][0], av[kc].x, av[kc].y, av[kc].z, av[kc].w,
                             b1[0], b1[1]);
                    mma16816(tmp[1][1], av[kc].x, av[kc].y, av[kc].z, av[kc].w,
                             b1[2], b1[3]);
                }
            }
            // fold inverse transform (coefs 0/+-1, compile-time pruned)
#pragma unroll
            for (int pi = 0; pi < 2; pi++)
#pragma unroll
                for (int tn = 0; tn < 2; tn++)
#pragma unroll
                    for (int c = 0; c < 4; c++) {
                        float m = tmp[pi][tn][c];
#pragma unroll
                        for (int a = 0; a < 2; a++) {
                            if (AR[a][pr] == 0.f) continue;
#pragma unroll
                            for (int b = 0; b < 2; b++) {
                                if (AR[b][pc] == 0.f) continue;
                                Y[pi][tn][a * 2 + b][c] +=
                                    AR[a][pr] * AR[b][pc] * m;
                            }
                        }
                    }
        }
    }

    // ---------------- epilogue: bias + GELU + per-pixel GN + store ----------
    const int ocr = wid * 16 + (l >> 2);
    const float b_lo = __ldg(bias + ocr), b_hi = __ldg(bias + ocr + 8);
    const float w_lo = __ldg(gnw + ocr),  w_hi = __ldg(gnw + ocr + 8);
    const float a_lo = __ldg(gnb + ocr),  a_hi = __ldg(gnb + ocr + 8);

#pragma unroll
    for (int pi = 0; pi < 2; pi++) {
#pragma unroll
        for (int tn = 0; tn < 2; tn++) {
            float g[4][4], o[4][4];
#pragma unroll
            for (int ab = 0; ab < 4; ab++) {
                g[0][ab] = gelu_tanh(Y[pi][tn][ab][0] + b_lo);
                g[1][ab] = gelu_tanh(Y[pi][tn][ab][1] + b_lo);
                g[2][ab] = gelu_tanh(Y[pi][tn][ab][2] + b_hi);
                g[3][ab] = gelu_tanh(Y[pi][tn][ab][3] + b_hi);
            }
#pragma unroll
            for (int u = 0; u < 2; u++)
#pragma unroll
                for (int ab = 0; ab < 4; ab++) {
                    float v0 = g[u][ab], v1 = g[u + 2][ab];
                    float s1 = v0 + v1, s2 = v0 * v0 + v1 * v1;
#pragma unroll
                    for (int m = 4; m <= 16; m <<= 1) {
                        s1 += __shfl_xor_sync(0xffffffffu, s1, m);
                        s2 += __shfl_xor_sync(0xffffffffu, s2, m);
                    }
                    float mean = s1 * (1.0f / 16.0f);
                    float var  = s2 * (1.0f / 16.0f) - mean * mean;
                    float rstd = rsqrtf(var + 1e-5f);
                    o[u][ab]     = (v0 - mean) * rstd * w_lo + a_lo;
                    o[u + 2][ab] = (v1 - mean) * rstd * w_hi + a_hi;
                }
            int colbase = ps * 64 + 32 * pi + 16 * tn + 4 * (l & 3);
#pragma unroll
            for (int rr = 0; rr < 2; rr++) {
                int oc = ocr + rr * 8;
#pragma unroll
                for (int a = 0; a < 2; a++) {
                    float* dst = out + (((size_t)n * COUT + oc) * HH +
                                        (2 * hb + a)) * WW + colbase;
                    *(float4*)dst = make_float4(o[rr * 2 + 0][a * 2 + 0],
                                                o[rr * 2 + 0][a * 2 + 1],
                                                o[rr * 2 + 1][a * 2 + 0],
                                                o[rr * 2 + 1][a * 2 + 1]);
                }
            }
        }
    }
}

extern "C" void kernel_launch(void* const* d_in, const int* in_sizes, int n_in,
                              void* d_out, int out_size) {
    const float* x   = (const float*)d_in[0];
    const float* w   = (const float*)d_in[1];
    const float* b   = (const float*)d_in[2];
    const float* gnw = (const float*)d_in[3];
    const float* gnb = (const float*)d_in[4];
    float* out = (float*)d_out;

    prep_all<<<32 + HH * NB, 256>>>(w, x);

    cudaFuncSetAttribute(convt_wino_kernel,
                         cudaFuncAttributeMaxDynamicSharedMemorySize, SMEM_SZ);
    convt_wino_kernel<<<dim3(HH, NB), 256, SMEM_SZ>>>(b, gnw, gnb, out);
}